// round 17
// baseline (speedup 1.0000x reference)
#include <cuda_runtime.h>
#include <cuda_fp16.h>
#include <cstdint>

#define NF       40960
#define MDIM     256
#define NB       2048
#define ROWS     (2*NB)          // 4096 feature rows (white then black)
#define CHUNK_V4 1280            // float4s per warp chunk (NF/4/8)
#define NSEG     8               // segments per row (one per eighth)
#define SEG_CAP  32              // capacity per segment

#define HALF_POS  (NB/2)         // 1024 positions per pipeline stage
#define HALF_SCAN NB             // 2048 scan CTAs per stage (2 rows/position)
#define TR_X      (NF/32)        // 1280
#define TR_Y      (MDIM/32)      // 8
#define TR_CTAS   (TR_X*TR_Y)    // 10240

// fp16 transposed feature-transformer weights: ft_wT[f][m], 21 MB
__device__ __half g_ftwT[NF * MDIM];
// Per-(row, eighth) compact feature-index lists + counts (deterministic order)
__device__ int g_list[ROWS * NSEG * SEG_CAP];   // 4 MB
__device__ int g_scnt[ROWS * NSEG];

__device__ __forceinline__ float clamp01(float x) {
    return fminf(fmaxf(x, 0.0f), 1.0f);
}

__device__ __forceinline__ float4 ld_row4h(int f, int m4) {
    const uint2 u = reinterpret_cast<const uint2*>(g_ftwT + (size_t)f * MDIM)[m4];
    const __half2 h0 = *reinterpret_cast<const __half2*>(&u.x);
    const __half2 h1 = *reinterpret_cast<const __half2*>(&u.y);
    const float2 f0 = __half22float2(h0);
    const float2 f1 = __half22float2(h1);
    return make_float4(f0.x, f0.y, f1.x, f1.y);
}

// ---------------------------------------------------------------------------
// Scan body: one CTA scans one feature row (warp per eighth) -> segment lists.
// ---------------------------------------------------------------------------
__device__ __forceinline__ void scan_row_body(
    const float* __restrict__ wf,
    const float* __restrict__ bfeat,
    int row)
{
    const int lane   = threadIdx.x & 31;
    const int eighth = threadIdx.x >> 5;

    const float* rowp = (row < NB) ? (wf + (size_t)row * NF)
                                   : (bfeat + (size_t)(row - NB) * NF);
    const uint4* p = reinterpret_cast<const uint4*>(rowp) + eighth * CHUNK_V4;
    int* list = g_list + ((size_t)row * NSEG + eighth) * SEG_CAP;

    int base = 0;   // warp-uniform count so far

    #pragma unroll
    for (int t = 0; t < 5; t++) {
        unsigned mask = 0u;
        #pragma unroll
        for (int g = 0; g < 2; g++) {
            uint4 v0 = __ldcs(&p[t * 256 + (g * 4 + 0) * 32 + lane]);
            uint4 v1 = __ldcs(&p[t * 256 + (g * 4 + 1) * 32 + lane]);
            uint4 v2 = __ldcs(&p[t * 256 + (g * 4 + 2) * 32 + lane]);
            uint4 v3 = __ldcs(&p[t * 256 + (g * 4 + 3) * 32 + lane]);
            const int s = g * 16;
            if (v0.x) mask |= 1u << (s + 0);  if (v0.y) mask |= 1u << (s + 1);
            if (v0.z) mask |= 1u << (s + 2);  if (v0.w) mask |= 1u << (s + 3);
            if (v1.x) mask |= 1u << (s + 4);  if (v1.y) mask |= 1u << (s + 5);
            if (v1.z) mask |= 1u << (s + 6);  if (v1.w) mask |= 1u << (s + 7);
            if (v2.x) mask |= 1u << (s + 8);  if (v2.y) mask |= 1u << (s + 9);
            if (v2.z) mask |= 1u << (s + 10); if (v2.w) mask |= 1u << (s + 11);
            if (v3.x) mask |= 1u << (s + 12); if (v3.y) mask |= 1u << (s + 13);
            if (v3.z) mask |= 1u << (s + 14); if (v3.w) mask |= 1u << (s + 15);
        }

        const unsigned bal = __ballot_sync(0xffffffffu, mask != 0u);
        if (bal) {
            const int c = __popc(mask);
            int inc = c;
            #pragma unroll
            for (int d = 1; d < 32; d <<= 1) {
                const int n = __shfl_up_sync(0xffffffffu, inc, d);
                if (lane >= d) inc += n;
            }
            const int exc   = inc - c;
            const int total = __shfl_sync(0xffffffffu, inc, 31);
            unsigned mm = mask;
            int k = 0;
            while (mm) {
                const int bb = __ffs(mm) - 1;
                mm &= mm - 1u;
                const int f = eighth * 5120
                            + (t * 256 + (bb >> 2) * 32 + lane) * 4 + (bb & 3);
                const int slot = base + exc + k;
                if (slot < SEG_CAP) list[slot] = f;
                k++;
            }
            base += total;
        }
    }
    if (lane == 0)
        g_scnt[row * NSEG + eighth] = (base < SEG_CAP) ? base : SEG_CAP;
}

// ---------------------------------------------------------------------------
// Transpose body: 32x32 tile of ft_w -> fp16 g_ftwT
// ---------------------------------------------------------------------------
__device__ __forceinline__ void transpose_body(const float* __restrict__ ft_w, int tb)
{
    __shared__ float tile[32][33];
    const int f0 = (tb % TR_X) * 32;
    const int m0 = (tb / TR_X) * 32;
    const int t  = threadIdx.x;
    {
        const int m = t >> 3;
        const int q = t & 7;
        const float4 v = *reinterpret_cast<const float4*>(
            ft_w + (size_t)(m0 + m) * NF + f0 + q * 4);
        tile[m][q * 4 + 0] = v.x;
        tile[m][q * 4 + 1] = v.y;
        tile[m][q * 4 + 2] = v.z;
        tile[m][q * 4 + 3] = v.w;
    }
    __syncthreads();
    {
        const int f  = t >> 3;
        const int m4 = t & 7;
        float4 v;
        v.x = tile[m4 * 4 + 0][f];
        v.y = tile[m4 * 4 + 1][f];
        v.z = tile[m4 * 4 + 2][f];
        v.w = tile[m4 * 4 + 3][f];
        union { __half2 h[2]; uint2 u; } cv;
        cv.h[0] = __floats2half2_rn(v.x, v.y);
        cv.h[1] = __floats2half2_rn(v.z, v.w);
        *reinterpret_cast<uint2*>(
            g_ftwT + (size_t)(f0 + f) * MDIM + m0 + m4 * 4) = cv.u;
    }
}

// ---------------------------------------------------------------------------
// Gather body: compaction + interleaved fp16 gather + MLP tail for position b.
// (identical logic to the 119.3us round-16 kernel)
// ---------------------------------------------------------------------------
__device__ __forceinline__ void gather_body(
    int b,
    const float* __restrict__ stm,
    const float* __restrict__ ft_b,
    const float* __restrict__ l1_w,
    const float* __restrict__ l1_b,
    const float* __restrict__ l2_w,
    const float* __restrict__ l2_b,
    const float* __restrict__ l3_w,
    const float* __restrict__ l3_b,
    float* __restrict__ out)
{
    const int tid  = threadIdx.x;
    const int lane = tid & 31;
    const int wid  = tid >> 5;
    const int m4   = tid & 63;
    const int grp  = tid >> 6;

    __shared__ __align__(16) float s_h[512];
    __shared__ __align__(16) float s_pW[4 * 256];
    __shared__ __align__(16) float s_pB[4 * 256];
    __shared__ __align__(16) int   s_idxW[NSEG * SEG_CAP];
    __shared__ __align__(16) int   s_idxB[NSEG * SEG_CAP];
    __shared__ float s_l2w[32 * 33];
    __shared__ float s_l2x[32];
    __shared__ int   s_cntW[8], s_cntB[8];
    __shared__ int   s_nW, s_nB;

    if (tid < 8)       s_cntW[tid]     = __ldcv(&g_scnt[b * NSEG + tid]);
    else if (tid < 16) s_cntB[tid - 8] = __ldcv(&g_scnt[(NB + b) * NSEG + (tid - 8)]);

    #pragma unroll
    for (int i = tid; i < 1024; i += 256)
        s_l2w[(i >> 5) * 33 + (i & 31)] = l2_w[i];
    __syncthreads();

    {
        const int seg  = tid >> 5;
        const int slot = tid & 31;
        const int cW = s_cntW[seg];
        const int cB = s_cntB[seg];
        int offW = 0, offB = 0;
        #pragma unroll
        for (int i = 0; i < 7; i++) {
            if (i < seg) { offW += s_cntW[i]; offB += s_cntB[i]; }
        }
        const int fW = g_list[((size_t)b * NSEG + seg) * SEG_CAP + slot];
        const int fB = g_list[((size_t)(NB + b) * NSEG + seg) * SEG_CAP + slot];
        __syncthreads();
        if (slot < cW) s_idxW[offW + slot] = fW;
        if (slot < cB) s_idxB[offB + slot] = fB;
        if (tid == 255) {
            s_nW = offW + cW;
            s_nB = offB + cB;
        }
    }
    __syncthreads();

    {
        const int nW  = s_nW;
        const int nB  = s_nB;
        const int j1W = (nW * (grp + 1)) >> 2;
        const int j1B = (nB * (grp + 1)) >> 2;
        int jw = (nW * grp) >> 2;
        int jb = (nB * grp) >> 2;

        float4 aW = make_float4(0.f, 0.f, 0.f, 0.f);
        float4 aB = make_float4(0.f, 0.f, 0.f, 0.f);

        while (jw + 4 <= j1W && jb + 4 <= j1B) {
            const float4 w0 = ld_row4h(s_idxW[jw + 0], m4);
            const float4 w1 = ld_row4h(s_idxW[jw + 1], m4);
            const float4 w2 = ld_row4h(s_idxW[jw + 2], m4);
            const float4 w3 = ld_row4h(s_idxW[jw + 3], m4);
            const float4 b0 = ld_row4h(s_idxB[jb + 0], m4);
            const float4 b1 = ld_row4h(s_idxB[jb + 1], m4);
            const float4 b2 = ld_row4h(s_idxB[jb + 2], m4);
            const float4 b3 = ld_row4h(s_idxB[jb + 3], m4);
            aW.x += w0.x; aW.y += w0.y; aW.z += w0.z; aW.w += w0.w;
            aW.x += w1.x; aW.y += w1.y; aW.z += w1.z; aW.w += w1.w;
            aW.x += w2.x; aW.y += w2.y; aW.z += w2.z; aW.w += w2.w;
            aW.x += w3.x; aW.y += w3.y; aW.z += w3.z; aW.w += w3.w;
            aB.x += b0.x; aB.y += b0.y; aB.z += b0.z; aB.w += b0.w;
            aB.x += b1.x; aB.y += b1.y; aB.z += b1.z; aB.w += b1.w;
            aB.x += b2.x; aB.y += b2.y; aB.z += b2.z; aB.w += b2.w;
            aB.x += b3.x; aB.y += b3.y; aB.z += b3.z; aB.w += b3.w;
            jw += 4; jb += 4;
        }
        while (jw + 4 <= j1W) {
            const float4 w0 = ld_row4h(s_idxW[jw + 0], m4);
            const float4 w1 = ld_row4h(s_idxW[jw + 1], m4);
            const float4 w2 = ld_row4h(s_idxW[jw + 2], m4);
            const float4 w3 = ld_row4h(s_idxW[jw + 3], m4);
            aW.x += w0.x; aW.y += w0.y; aW.z += w0.z; aW.w += w0.w;
            aW.x += w1.x; aW.y += w1.y; aW.z += w1.z; aW.w += w1.w;
            aW.x += w2.x; aW.y += w2.y; aW.z += w2.z; aW.w += w2.w;
            aW.x += w3.x; aW.y += w3.y; aW.z += w3.z; aW.w += w3.w;
            jw += 4;
        }
        for (; jw < j1W; jw++) {
            const float4 v = ld_row4h(s_idxW[jw], m4);
            aW.x += v.x; aW.y += v.y; aW.z += v.z; aW.w += v.w;
        }
        while (jb + 4 <= j1B) {
            const float4 b0 = ld_row4h(s_idxB[jb + 0], m4);
            const float4 b1 = ld_row4h(s_idxB[jb + 1], m4);
            const float4 b2 = ld_row4h(s_idxB[jb + 2], m4);
            const float4 b3 = ld_row4h(s_idxB[jb + 3], m4);
            aB.x += b0.x; aB.y += b0.y; aB.z += b0.z; aB.w += b0.w;
            aB.x += b1.x; aB.y += b1.y; aB.z += b1.z; aB.w += b1.w;
            aB.x += b2.x; aB.y += b2.y; aB.z += b2.z; aB.w += b2.w;
            aB.x += b3.x; aB.y += b3.y; aB.z += b3.z; aB.w += b3.w;
            jb += 4;
        }
        for (; jb < j1B; jb++) {
            const float4 v = ld_row4h(s_idxB[jb], m4);
            aB.x += v.x; aB.y += v.y; aB.z += v.z; aB.w += v.w;
        }

        reinterpret_cast<float4*>(&s_pW[grp * 256])[m4] = aW;
        reinterpret_cast<float4*>(&s_pB[grp * 256])[m4] = aB;
    }
    __syncthreads();

    {
        const float bias = ft_b[tid];
        const float accW = bias + s_pW[tid] + s_pW[256 + tid]
                                + s_pW[512 + tid] + s_pW[768 + tid];
        const float accB = bias + s_pB[tid] + s_pB[256 + tid]
                                + s_pB[512 + tid] + s_pB[768 + tid];
        const float s = stm[b];
        s_h[tid]       = clamp01(s * accW + (1.0f - s) * accB);
        s_h[256 + tid] = clamp01(s * accB + (1.0f - s) * accW);
    }
    __syncthreads();

    {
        const float4* hv = reinterpret_cast<const float4*>(s_h);
        #pragma unroll
        for (int r = 0; r < 4; r++) {
            const int n = wid * 4 + r;
            const float4* wr = reinterpret_cast<const float4*>(l1_w + n * 512);
            float p = 0.0f;
            #pragma unroll
            for (int i = 0; i < 4; i++) {
                const float4 a = wr[i * 32 + lane];
                const float4 x = hv[i * 32 + lane];
                p += a.x * x.x;
                p += a.y * x.y;
                p += a.z * x.z;
                p += a.w * x.w;
            }
            p += __shfl_down_sync(0xffffffffu, p, 16);
            p += __shfl_down_sync(0xffffffffu, p, 8);
            p += __shfl_down_sync(0xffffffffu, p, 4);
            p += __shfl_down_sync(0xffffffffu, p, 2);
            p += __shfl_down_sync(0xffffffffu, p, 1);
            if (lane == 0) s_l2x[n] = clamp01(p + l1_b[n]);
        }
    }
    __syncthreads();

    if (tid < 32) {
        float q = l2_b[tid];
        #pragma unroll
        for (int k = 0; k < 32; k++) q += s_l2w[tid * 33 + k] * s_l2x[k];
        const float l3x = clamp01(q);
        float t = l3x * l3_w[tid];
        #pragma unroll
        for (int off = 16; off > 0; off >>= 1)
            t += __shfl_down_sync(0xffffffffu, t, off);
        if (tid == 0) {
            const float ev = clamp01(t + l3_b[0]);
            out[b] = (ev - 0.5f) * 2.0f * 10000.0f;
        }
    }
}

// ---------------------------------------------------------------------------
// K1: scan half A (rows for positions 0..1023, both colors) + transpose
// ---------------------------------------------------------------------------
__global__ __launch_bounds__(256) void k1_scanA_transpose(
    const float* __restrict__ wf,
    const float* __restrict__ bfeat,
    const float* __restrict__ ft_w)
{
    if (blockIdx.x < HALF_SCAN) {
        const int sc  = blockIdx.x;
        const int row = (sc < HALF_POS) ? sc : (NB + (sc - HALF_POS));
        scan_row_body(wf, bfeat, row);
    } else {
        transpose_body(ft_w, blockIdx.x - HALF_SCAN);
    }
}

// ---------------------------------------------------------------------------
// K2: scan half B (positions 1024..2047) + gather half A (positions 0..1023)
// Scan CTAs first (long pole), gather CTAs backfill.
// ---------------------------------------------------------------------------
__global__ __launch_bounds__(256) void k2_scanB_gatherA(
    const float* __restrict__ wf,
    const float* __restrict__ bfeat,
    const float* __restrict__ stm,
    const float* __restrict__ ft_b,
    const float* __restrict__ l1_w,
    const float* __restrict__ l1_b,
    const float* __restrict__ l2_w,
    const float* __restrict__ l2_b,
    const float* __restrict__ l3_w,
    const float* __restrict__ l3_b,
    float* __restrict__ out)
{
    if (blockIdx.x < HALF_SCAN) {
        const int sc  = blockIdx.x;
        const int row = (sc < HALF_POS) ? (HALF_POS + sc)
                                        : (NB + HALF_POS + (sc - HALF_POS));
        scan_row_body(wf, bfeat, row);
    } else {
        const int b = blockIdx.x - HALF_SCAN;   // 0..1023
        gather_body(b, stm, ft_b, l1_w, l1_b, l2_w, l2_b, l3_w, l3_b, out);
    }
}

// ---------------------------------------------------------------------------
// K3: gather half B (positions 1024..2047)
// ---------------------------------------------------------------------------
__global__ __launch_bounds__(256) void k3_gatherB(
    const float* __restrict__ stm,
    const float* __restrict__ ft_b,
    const float* __restrict__ l1_w,
    const float* __restrict__ l1_b,
    const float* __restrict__ l2_w,
    const float* __restrict__ l2_b,
    const float* __restrict__ l3_w,
    const float* __restrict__ l3_b,
    float* __restrict__ out)
{
    gather_body(HALF_POS + blockIdx.x, stm, ft_b, l1_w, l1_b,
                l2_w, l2_b, l3_w, l3_b, out);
}

// ---------------------------------------------------------------------------
// Launch
// ---------------------------------------------------------------------------
extern "C" void kernel_launch(void* const* d_in, const int* in_sizes, int n_in,
                              void* d_out, int out_size)
{
    const float* wf    = (const float*)d_in[0];
    const float* bfeat = (const float*)d_in[1];
    const float* stm   = (const float*)d_in[2];
    const float* ft_w  = (const float*)d_in[3];
    const float* ft_b  = (const float*)d_in[4];
    const float* l1_w  = (const float*)d_in[5];
    const float* l1_b  = (const float*)d_in[6];
    const float* l2_w  = (const float*)d_in[7];
    const float* l2_b  = (const float*)d_in[8];
    const float* l3_w  = (const float*)d_in[9];
    const float* l3_b  = (const float*)d_in[10];
    float* out = (float*)d_out;

    k1_scanA_transpose<<<HALF_SCAN + TR_CTAS, 256>>>(wf, bfeat, ft_w);

    k2_scanB_gatherA<<<HALF_SCAN + HALF_POS, 256>>>(wf, bfeat, stm, ft_b,
                                                    l1_w, l1_b, l2_w, l2_b,
                                                    l3_w, l3_b, out);

    k3_gatherB<<<HALF_POS, 256>>>(stm, ft_b, l1_w, l1_b, l2_w, l2_b,
                                  l3_w, l3_b, out);
}